// round 17
// baseline (speedup 1.0000x reference)
#include <cuda_runtime.h>
#include <cuda_fp16.h>
#include <math.h>

#define B_ROWS 4096
#define T_LEN  8192
#define SCAN_THREADS 512
#define NWARPS (SCAN_THREADS / 32)     // 16
#define CHUNK (T_LEN / SCAN_THREADS)   // 16
#define GROUPS (T_LEN / 4)             // 2048 float4-groups per row
#define GAMMA 0.99f
#define GAMMA16 0.8514577710948755f    // 0.99^16
#define EPS_N 1e-9f
#define RPAD 513                       // padded row stride (words) for transpose smem

// Scratch (device globals; no allocations allowed).
__device__ float    g_row_sum[B_ROWS];
__device__ float    g_row_inv[B_ROWS];
__device__ float    g_mean_val;
__device__ unsigned g_count;           // zero-init; atomicInc wraps -> self-reset per launch
// fp16 staging for unnormalized returns: 64 MB, L2-resident in steady state.
__device__ __align__(128) __half g_ret_h[(size_t)B_ROWS * T_LEN];

// ───────────────────────── scan: one block per row ─────────────────────────
// x_t = r_t + a_t * x_{t+1},  a_t = GAMMA*(1-done_t),  done in {0,1} exactly.
// R16 core, minus the dones smem round-trip: owners load their own dones
// directly (strided is proven non-binding here) while rewards transpose runs.
__global__ __launch_bounds__(SCAN_THREADS, 4)
void scan_kernel(const float* __restrict__ rewards,
                 const float* __restrict__ dones)
{
    const int row  = blockIdx.x;
    const int tid  = threadIdx.x;
    const int lane = tid & 31;
    const int wid  = tid >> 5;
    const size_t row_off = (size_t)row * T_LEN;

    __shared__ float s_rew[16 * RPAD];          // transposed reward values
    __shared__ float sWA[NWARPS], sWB[NWARPS], sCB[NWARPS];
    __shared__ float sS[NWARPS],  sQ[NWARPS];
    __shared__ unsigned s_last;

    // ── Front-batch OWN dones (4 strided float4; in flight through phase 1) ──
    const float4* dp = reinterpret_cast<const float4*>(dones + row_off) + tid * (CHUNK / 4);
    float4 dv0 = __ldcs(dp + 0);
    float4 dv1 = __ldcs(dp + 1);
    float4 dv2 = __ldcs(dp + 2);
    float4 dv3 = __ldcs(dp + 3);

    // ── Phase 1: coalesced reward load -> transposed smem ──
    const float4* r4 = reinterpret_cast<const float4*>(rewards + row_off);
#pragma unroll
    for (int k = 0; k < 4; k++) {
        const int g = tid + 512 * k;
        float4 rv = __ldcs(r4 + g);
        const int c = (g & 3) * 4;
        const int q = g >> 2;
        s_rew[(c + 0) * RPAD + q] = rv.x;
        s_rew[(c + 1) * RPAD + q] = rv.y;
        s_rew[(c + 2) * RPAD + q] = rv.z;
        s_rew[(c + 3) * RPAD + q] = rv.w;
    }

    // Build done mask in registers (bit t -> done at element tid*16+t).
    unsigned mask = 0;
    mask |= (dv0.x != 0.0f ? 1u  : 0u) | (dv0.y != 0.0f ? 2u    : 0u)
          | (dv0.z != 0.0f ? 4u  : 0u) | (dv0.w != 0.0f ? 8u    : 0u);
    mask |= (dv1.x != 0.0f ? 16u : 0u) | (dv1.y != 0.0f ? 32u   : 0u)
          | (dv1.z != 0.0f ? 64u : 0u) | (dv1.w != 0.0f ? 128u  : 0u);
    mask |= (dv2.x != 0.0f ? 256u: 0u) | (dv2.y != 0.0f ? 512u  : 0u)
          | (dv2.z != 0.0f ? 1024u:0u) | (dv2.w != 0.0f ? 2048u : 0u);
    mask |= (dv3.x != 0.0f ? 4096u:0u) | (dv3.y != 0.0f ? 8192u : 0u)
          | (dv3.z != 0.0f ?16384u:0u) | (dv3.w != 0.0f ? 32768u: 0u);
    __syncthreads();

    // ── Phase 2: compose chunk affine map, reading values from smem ──
    float A  = (mask == 0u) ? GAMMA16 : 0.0f;
    float Bc = 0.0f;
#pragma unroll
    for (int t = CHUNK - 1; t >= 0; t--) {
        float v = s_rew[t * RPAD + tid];        // conflict-free (lane-contiguous)
        float f = fmaf(GAMMA, Bc, v);
        Bc = (mask & (1u << t)) ? v : f;
    }

    // Warp-level inclusive SUFFIX scan via shuffles.
#pragma unroll
    for (int d = 1; d < 32; d <<= 1) {
        float A2 = __shfl_down_sync(0xFFFFFFFFu, A, d);
        float B2 = __shfl_down_sync(0xFFFFFFFFu, Bc, d);
        if (lane + d < 32) {
            Bc = fmaf(A, B2, Bc);
            A  = A * A2;
        }
    }

    if (lane == 0) { sWA[wid] = A; sWB[wid] = Bc; }
    __syncthreads();

    if (wid == 0) {
        float wA = (lane < NWARPS) ? sWA[lane] : 1.0f;
        float wB = (lane < NWARPS) ? sWB[lane] : 0.0f;
#pragma unroll
        for (int d = 1; d < NWARPS; d <<= 1) {
            float A2 = __shfl_down_sync(0xFFFFFFFFu, wA, d);
            float B2 = __shfl_down_sync(0xFFFFFFFFu, wB, d);
            if (lane + d < NWARPS) {
                wB = fmaf(wA, B2, wB);
                wA = wA * A2;
            }
        }
        float eB = __shfl_down_sync(0xFFFFFFFFu, wB, 1);
        if (lane == NWARPS - 1) eB = 0.0f;
        if (lane < NWARPS) sCB[lane] = eB;
    }
    __syncthreads();

    float cB   = sCB[wid];
    float totB = fmaf(A, cB, Bc);
    float carry = __shfl_down_sync(0xFFFFFFFFu, totB, 1);
    if (lane == 31) carry = cB;        // tid==511 -> cB==0, correct

    // ── Phase 3: replay from smem with INLINE fp16 packing ──
    float sum = 0.0f, sq = 0.0f;
    float held = 0.0f;
    __half2 h[CHUNK / 2];
#pragma unroll
    for (int t = CHUNK - 1; t >= 0; t--) {
        float v = s_rew[t * RPAD + tid];
        float f = fmaf(GAMMA, carry, v);
        carry = (mask & (1u << t)) ? v : f;
        sum += carry;
        sq = fmaf(carry, carry, sq);
        if (t & 1) held = carry;
        else       h[t >> 1] = __floats2half2_rn(carry, held);
    }

    // ── Phase 4: thread-contiguous staging store (32B/thread, 2x STG.128) ──
    {
        uint4* dst = reinterpret_cast<uint4*>(g_ret_h + row_off + tid * CHUNK);
        const uint4* srcv = reinterpret_cast<const uint4*>(h);
        dst[0] = srcv[0];
        dst[1] = srcv[1];
    }

    // Block reduction of (sum, sq).
#pragma unroll
    for (int d = 16; d > 0; d >>= 1) {
        sum += __shfl_down_sync(0xFFFFFFFFu, sum, d);
        sq  += __shfl_down_sync(0xFFFFFFFFu, sq,  d);
    }
    if (lane == 0) { sS[wid] = sum; sQ[wid] = sq; }
    __syncthreads();
    if (tid < 32) {
        float ts = (lane < NWARPS) ? sS[lane] : 0.0f;
        float tq = (lane < NWARPS) ? sQ[lane] : 0.0f;
#pragma unroll
        for (int d = NWARPS / 2; d > 0; d >>= 1) {
            ts += __shfl_down_sync(0xFFFFFFFFu, ts, d);
            tq += __shfl_down_sync(0xFFFFFFFFu, tq, d);
        }
        if (lane == 0) {
            float mean = ts / (float)T_LEN;
            float var  = (tq - ts * mean) / (float)(T_LEN - 1);   // ddof=1
            g_row_sum[row] = ts;
            g_row_inv[row] = 1.0f / (sqrtf(fmaxf(var, 0.0f)) + EPS_N);
        }
    }

    // Last block to finish reduces the 4096 row sums -> global mean.
    if (tid == 0) {
        __threadfence();
        unsigned prev = atomicInc(&g_count, B_ROWS - 1);   // wraps to 0: self-reset
        s_last = (prev == B_ROWS - 1) ? 1u : 0u;
    }
    __syncthreads();
    if (s_last) {
        float s = 0.0f;
#pragma unroll
        for (int i = 0; i < B_ROWS / SCAN_THREADS; i++)
            s += __ldcg(&g_row_sum[tid + i * SCAN_THREADS]);
#pragma unroll
        for (int d = 16; d > 0; d >>= 1)
            s += __shfl_down_sync(0xFFFFFFFFu, s, d);
        if (lane == 0) sS[wid] = s;
        __syncthreads();
        if (tid < 32) {
            float t = (lane < NWARPS) ? sS[lane] : 0.0f;
#pragma unroll
            for (int d = 16; d > 0; d >>= 1)
                t += __shfl_down_sync(0xFFFFFFFFu, t, d);
            if (tid == 0)
                g_mean_val = t / ((float)B_ROWS * (float)T_LEN);
        }
    }
}

// ── normalize: R13/R16-proven config (best measured). One block per row; 512
// threads, 4 unit-interleaved __ldlu loads (unit = 4 elements), __stcs out. ──
#define GROUPS_PER_ROW GROUPS
__global__ __launch_bounds__(512)
void norm_kernel(float* __restrict__ out)
{
    const int row = blockIdx.x;
    const float inv = g_row_inv[row];
    const float neg = -g_mean_val * inv;
    const size_t unit0 = (size_t)row * GROUPS_PER_ROW + threadIdx.x;

    const uint2* src = reinterpret_cast<const uint2*>(g_ret_h);
    float4* o4 = reinterpret_cast<float4*>(out);

    uint2 p[4];
#pragma unroll
    for (int k = 0; k < 4; k++)
        p[k] = __ldlu(src + unit0 + 512 * k);     // front-batched, coalesced

#pragma unroll
    for (int k = 0; k < 4; k++) {
        __half2 h0 = *reinterpret_cast<__half2*>(&p[k].x);
        __half2 h1 = *reinterpret_cast<__half2*>(&p[k].y);
        float2 a = __half22float2(h0);
        float2 b = __half22float2(h1);
        float4 v;
        v.x = fmaf(a.x, inv, neg);
        v.y = fmaf(a.y, inv, neg);
        v.z = fmaf(b.x, inv, neg);
        v.w = fmaf(b.y, inv, neg);
        __stcs(o4 + unit0 + 512 * k, v);
    }
}

extern "C" void kernel_launch(void* const* d_in, const int* in_sizes, int n_in,
                              void* d_out, int out_size)
{
    const float* rewards = (const float*)d_in[0];
    const float* dones   = (const float*)d_in[1];
    float* out = (float*)d_out;

    scan_kernel<<<B_ROWS, SCAN_THREADS>>>(rewards, dones);
    norm_kernel<<<B_ROWS, 512>>>(out);
}